// round 8
// baseline (speedup 1.0000x reference)
#include <cuda_runtime.h>
#include <cuda_bf16.h>

// ---------------------------------------------------------------------------
// BoardModel: board build + LeNet + (collapsed) MHA + FC head.
// Key insights:
//  (1) kv seq-len == 1 -> softmax == 1 -> attention collapses:
//      a_mean = out_w @ (vw @ b2 + vb) + out_b.  emb/pe/q/k are dead code.
//  (2) conv1 channels 1,2 = constant pad FRAME (row21/col0/col11 = 1.0)
//      + 4 piece cells. Conv is linear pre-ReLU:
//        - frame part is sample-independent -> precomputed table F[oc][22][12]
//          built once per block from (w1+w2);
//        - piece cells -> 5x5 weight stamps per cell;
//        - dense conv runs over channel 0 only (-2/3 of conv1 FMA work).
// One warp per sample; weights staged in shared memory once per block.
// Board in SMEM at ROW STRIDE 13 -> conflict-free conv1 patch loads.
// conv1: 2 pooled cells (8 conv outputs) per lane-task, 8 FMAs/weight LDS.
// conv2: task = (oc, oy-half), 6 outputs per lane, 6 FMAs/weight LDS.
// board output: gather from stride-13 + STG.128 streaming store.
// ---------------------------------------------------------------------------

#define WARPS_PER_BLOCK 8
#define NTHREADS (WARPS_PER_BLOCK * 32)

// weight shared-memory offsets (floats)
#define OFF_C1W 0        // 6*3*5*5   = 450
#define OFF_C1B 450      // 6
#define OFF_C2W 456      // 16*6*5*5  = 2400
#define OFF_C2B 2856     // 16
#define OFF_C3W 2872     // 64*16*3   = 3072
#define OFF_C3B 5944     // 64
#define OFF_L1W 6008     // 32*64     = 2048
#define OFF_L1B 8056     // 32
#define OFF_FCW 8088     // 32*8      = 256
#define OFF_FCB 8344     // 32
#define OFF_VW  8376     // 32*32     = 1024  (in_proj_w rows 64..95)
#define OFF_VB  9400     // 32        (in_proj_b[64..95])
#define OFF_OW  9432     // 32*32     = 1024
#define OFF_OB  10456    // 32
#define OFF_FRM 10488    // 6*22*12   = 1584  (ch1+ch2 frame conv table)
#define WTOT    12072    // multiple of 4 -> per-warp scratch 16B-aligned

// board row stride in SMEM (bank-conflict-avoiding; semantic width is 12)
#define BSTRIDE 13

// per-warp scratch offsets (floats)
#define S_BOARD 0                   // 3*22*13 = 858 (stride-13 board)
#define S_P1    858                 // 6*11*6  = 396 (pooled conv1)
#define S_C2    (858+396)           // 16*6*2  = 192 (conv2 rows 0..5)
#define S_P2    (S_C2+192)          // 16*3    = 48
#define S_FEAT  (S_P2+48)           // 64
#define S_B2    (S_FEAT+64)         // 32
#define S_V     (S_B2+32)           // 32
#define SCR_STRIDE 1624             // used: 1622; multiple of 4

__global__ void __launch_bounds__(NTHREADS)
board_model_kernel(const int* __restrict__ t,
                   const int* __restrict__ piece_table,
                   const float* __restrict__ c1w, const float* __restrict__ c1b,
                   const float* __restrict__ c2w, const float* __restrict__ c2b,
                   const float* __restrict__ c3w, const float* __restrict__ c3b,
                   const float* __restrict__ l1w, const float* __restrict__ l1b,
                   const float* __restrict__ fcw, const float* __restrict__ fcb,
                   const float* __restrict__ ipw, const float* __restrict__ ipb,
                   const float* __restrict__ opw, const float* __restrict__ opb,
                   float* __restrict__ out, float* __restrict__ board_out,
                   int bsz, int write_board)
{
    extern __shared__ float sm[];
    float* w = sm;
    const int tid = threadIdx.x;

    // ---- stage weights into shared memory (cooperative, whole block) ----
    for (int i = tid; i < 450;  i += NTHREADS) w[OFF_C1W + i] = c1w[i];
    for (int i = tid; i < 6;    i += NTHREADS) w[OFF_C1B + i] = c1b[i];
    for (int i = tid; i < 2400; i += NTHREADS) w[OFF_C2W + i] = c2w[i];
    for (int i = tid; i < 16;   i += NTHREADS) w[OFF_C2B + i] = c2b[i];
    for (int i = tid; i < 3072; i += NTHREADS) w[OFF_C3W + i] = c3w[i];
    for (int i = tid; i < 64;   i += NTHREADS) w[OFF_C3B + i] = c3b[i];
    for (int i = tid; i < 2048; i += NTHREADS) w[OFF_L1W + i] = l1w[i];
    for (int i = tid; i < 32;   i += NTHREADS) w[OFF_L1B + i] = l1b[i];
    for (int i = tid; i < 256;  i += NTHREADS) w[OFF_FCW + i] = fcw[i];
    for (int i = tid; i < 32;   i += NTHREADS) w[OFF_FCB + i] = fcb[i];
    for (int i = tid; i < 1024; i += NTHREADS) w[OFF_VW  + i] = ipw[64 * 32 + i];
    for (int i = tid; i < 32;   i += NTHREADS) w[OFF_VB  + i] = ipb[64 + i];
    for (int i = tid; i < 1024; i += NTHREADS) w[OFF_OW  + i] = opw[i];
    for (int i = tid; i < 32;   i += NTHREADS) w[OFF_OB  + i] = opb[i];
    __syncthreads();

    // ---- build F[oc][oy][ox]: conv response of (ch1+ch2) pad frame ----
    // frame = {iy==21} U {ix==0} U {ix==11} within the padded 22x12 board.
    for (int i = tid; i < 1584; i += NTHREADS) {
        int oc  = i / 264;
        int rem = i % 264;
        int oy  = rem / 12, ox = rem % 12;
        const float* w1k = w + OFF_C1W + (oc * 3 + 1) * 25;
        const float* w2k = w1k + 25;
        float f = 0.f;
        #pragma unroll
        for (int ky = 0; ky < 5; ky++) {
            int iy = oy - 2 + ky;
            if (iy < 0 || iy > 21) continue;
            #pragma unroll
            for (int kx = 0; kx < 5; kx++) {
                int ix = ox - 2 + kx;
                if (ix < 0 || ix > 11) continue;
                if (iy == 21 || ix == 0 || ix == 11)
                    f += w1k[ky * 5 + kx] + w2k[ky * 5 + kx];
            }
        }
        w[OFF_FRM + i] = f;
    }
    __syncthreads();

    const int warp = tid >> 5;
    const int lane = tid & 31;
    const int sample = blockIdx.x * WARPS_PER_BLOCK + warp;
    if (sample >= bsz) return;

    float* s = sm + WTOT + warp * SCR_STRIDE;
    const int* trow = t + (long)sample * 232;

    // ---- build padded board [3][22][12] at SMEM row stride 13 ----
    // rows 0..20 cols 1..10 are interior; row 21 and cols 0,11 are pad=1.
    for (int p = lane; p < 792; p += 32) {
        int c  = p % 12;
        int rc = p / 12;
        int r  = rc % 22;
        int ch = rc / 22;
        float v;
        if (r == 21 || c == 0 || c == 11)      v = 1.0f;
        else if (ch == 0)                       v = (float)trow[22 + r * 10 + (c - 1)];
        else                                    v = 0.0f;
        s[S_BOARD + (ch * 22 + r) * BSTRIDE + c] = v;
    }
    __syncwarp();

    // ---- piece cells: argsort(1-pieces,stable)[:4] == first 4 one-cells in
    // raster order (then empties). ALL lanes compute (uniform; needed for
    // the conv1 stamps); lane 0 also scatters into the SMEM board. ----
    int cX[4], cY1[4], cY2[4];   // padded col (x+1), ch1 row (y), ch2 row (ny)
    int cOK[4];
    {
        const int t1 = trow[1], t2 = trow[2], t3 = trow[3], t4 = trow[4], t8 = trow[8];
        const int* pt = piece_table + ((t8 * 4 + t4) * 16);
        int cells[4];
        int n = 0;
        #pragma unroll
        for (int i = 0; i < 16; i++) { if (n < 4 && pt[i] == 1) cells[n++] = i; }
        #pragma unroll
        for (int i = 0; i < 16; i++) { if (n < 4 && pt[i] != 1) cells[n++] = i; }
        #pragma unroll
        for (int k = 0; k < 4; k++) {
            int cy = cells[k] >> 2, cx = cells[k] & 3;
            int x  = cx + t1 - 2;
            int y  = cy + t2;
            int ny = y + t3;
            cOK[k] = (y >= 0 && ny >= 0 && x >= 0 && x < 10);
            cX[k]  = x + 1;
            cY1[k] = y;
            cY2[k] = ny;
            if (lane == 0 && cOK[k]) {
                if (y  < 21) s[S_BOARD + (1 * 22 + y ) * BSTRIDE + (x + 1)] = 1.0f;
                if (ny < 21) s[S_BOARD + (2 * 22 + ny) * BSTRIDE + (x + 1)] = 1.0f;
            }
        }
    }
    __syncwarp();

    // ---- write board output: gather from stride-13 board, STG.128 out ----
    if (write_board) {
        float4* bo4 = (float4*)(board_out + (long)sample * 792);
        for (int q = lane; q < 198; q += 32) {
            int b  = 4 * q;
            int c0 = b % 12;
            int rc = b / 12;
            const float* src = &s[S_BOARD + rc * BSTRIDE + c0];
            bo4[q] = make_float4(src[0], src[1], src[2], src[3]);
        }
    }

    // ---- conv1 (3->6, 5x5, pad 2) + ReLU + avgpool2, fused ----
    // Dense conv over channel 0; ch1/ch2 = frame table F + piece stamps.
    // Task = (oc, py, px-pair): 198 tasks; 8 conv outputs per task.
    for (int tp = lane; tp < 198; tp += 32) {
        int oc  = tp / 33;
        int rem = tp % 33;
        int py  = rem / 3, pxp = rem % 3;
        int y0 = 2 * py;          // top conv row of the quad
        int x0 = 4 * pxp;         // leftmost conv col of the 4-col group

        // frame contribution of ch1+ch2 (precomputed, sample-independent)
        const float* Foc = w + OFF_FRM + oc * 264;
        float acc[2][4];
        #pragma unroll
        for (int r = 0; r < 2; r++)
            #pragma unroll
            for (int c = 0; c < 4; c++)
                acc[r][c] = Foc[(y0 + r) * 12 + (x0 + c)];

        // dense channel 0
        {
            float patch[6][8];
            #pragma unroll
            for (int dy = 0; dy < 6; dy++) {
                int iy = y0 - 2 + dy;
                #pragma unroll
                for (int dx = 0; dx < 8; dx++) {
                    int ix = x0 - 2 + dx;
                    patch[dy][dx] = (iy >= 0 && iy < 22 && ix >= 0 && ix < 12)
                                  ? s[S_BOARD + iy * BSTRIDE + ix] : 0.f;
                }
            }
            const float* wk = w + OFF_C1W + (oc * 3) * 25;
            #pragma unroll
            for (int ky = 0; ky < 5; ky++) {
                #pragma unroll
                for (int kx = 0; kx < 5; kx++) {
                    float wv = wk[ky * 5 + kx];
                    #pragma unroll
                    for (int r = 0; r < 2; r++) {
                        acc[r][0] = fmaf(wv, patch[ky + r][kx    ], acc[r][0]);
                        acc[r][1] = fmaf(wv, patch[ky + r][kx + 1], acc[r][1]);
                        acc[r][2] = fmaf(wv, patch[ky + r][kx + 2], acc[r][2]);
                        acc[r][3] = fmaf(wv, patch[ky + r][kx + 3], acc[r][3]);
                    }
                }
            }
        }

        // piece-cell stamps for ch1, ch2 (cells are interior: rows<21, cols 1..10)
        const float* w1k = w + OFF_C1W + (oc * 3 + 1) * 25;
        const float* w2k = w1k + 25;
        #pragma unroll
        for (int k = 0; k < 4; k++) {
            if (!cOK[k]) continue;
            int dxx = cX[k] - x0 + 2;              // kx for c=0
            if ((unsigned)dxx > 7u) continue;      // no column overlap
            int dy1 = cY1[k] - y0 + 2;             // ky for r=0 (ch1)
            if (cY1[k] < 21 && (unsigned)dy1 <= 5u) {
                #pragma unroll
                for (int r = 0; r < 2; r++) {
                    int oy = dy1 - r;
                    if ((unsigned)oy < 5u) {
                        #pragma unroll
                        for (int c = 0; c < 4; c++) {
                            int ox = dxx - c;
                            if ((unsigned)ox < 5u) acc[r][c] += w1k[oy * 5 + ox];
                        }
                    }
                }
            }
            int dy2 = cY2[k] - y0 + 2;             // ky for r=0 (ch2)
            if (cY2[k] < 21 && (unsigned)dy2 <= 5u) {
                #pragma unroll
                for (int r = 0; r < 2; r++) {
                    int oy = dy2 - r;
                    if ((unsigned)oy < 5u) {
                        #pragma unroll
                        for (int c = 0; c < 4; c++) {
                            int ox = dxx - c;
                            if ((unsigned)ox < 5u) acc[r][c] += w2k[oy * 5 + ox];
                        }
                    }
                }
            }
        }

        float bb = w[OFF_C1B + oc];
        float p0 = 0.25f * (fmaxf(acc[0][0] + bb, 0.f) + fmaxf(acc[0][1] + bb, 0.f) +
                            fmaxf(acc[1][0] + bb, 0.f) + fmaxf(acc[1][1] + bb, 0.f));
        float p1 = 0.25f * (fmaxf(acc[0][2] + bb, 0.f) + fmaxf(acc[0][3] + bb, 0.f) +
                            fmaxf(acc[1][2] + bb, 0.f) + fmaxf(acc[1][3] + bb, 0.f));
        s[S_P1 + (oc * 11 + py) * 6 + 2 * pxp    ] = p0;
        s[S_P1 + (oc * 11 + py) * 6 + 2 * pxp + 1] = p1;
    }
    __syncwarp();

    // ---- conv2 (6->16, 5x5, valid) + ReLU. Rows 0..5 only (row 6 is
    // dropped by the pool). Task = (oc, half): 32 tasks, one per lane;
    // 6 outputs per task, 6 FMAs per weight LDS, 7x6 patch reuse. ----
    {
        int oc   = lane >> 1;           // 0..15
        int half = lane & 1;            // 0..1
        int oy0  = 3 * half;            // 0 or 3
        float bb = w[OFF_C2B + oc];
        float acc[3][2];
        #pragma unroll
        for (int r = 0; r < 3; r++) { acc[r][0] = bb; acc[r][1] = bb; }
        const float* w2 = w + OFF_C2W + oc * 150;
        #pragma unroll
        for (int ci = 0; ci < 6; ci++) {
            float patch[7][6];
            #pragma unroll
            for (int dy = 0; dy < 7; dy++) {
                const float* row = &s[S_P1 + (ci * 11 + oy0 + dy) * 6];
                #pragma unroll
                for (int dx = 0; dx < 6; dx++) patch[dy][dx] = row[dx];
            }
            const float* wc = &w2[ci * 25];
            #pragma unroll
            for (int ky = 0; ky < 5; ky++) {
                #pragma unroll
                for (int kx = 0; kx < 5; kx++) {
                    float wv = wc[ky * 5 + kx];
                    #pragma unroll
                    for (int r = 0; r < 3; r++) {
                        acc[r][0] = fmaf(wv, patch[r + ky][kx    ], acc[r][0]);
                        acc[r][1] = fmaf(wv, patch[r + ky][kx + 1], acc[r][1]);
                    }
                }
            }
        }
        #pragma unroll
        for (int r = 0; r < 3; r++) {
            s[S_C2 + (oc * 6 + oy0 + r) * 2 + 0] = fmaxf(acc[r][0], 0.f);
            s[S_C2 + (oc * 6 + oy0 + r) * 2 + 1] = fmaxf(acc[r][1], 0.f);
        }
    }
    __syncwarp();

    // ---- avgpool2 on conv2 -> [16][3] ----
    for (int p = lane; p < 48; p += 32) {
        int oc = p / 3, py = p % 3;
        const float* c2 = &s[S_C2 + (oc * 6 + 2 * py) * 2];
        s[S_P2 + p] = 0.25f * (c2[0] + c2[1] + c2[2] + c2[3]);
    }
    __syncwarp();

    // ---- conv3 (16->64, 3x1, valid) + ReLU -> feat[64] ----
    #pragma unroll
    for (int k = 0; k < 2; k++) {
        int o = lane + k * 32;
        float acc = w[OFF_C3B + o];
        const float* w3 = w + OFF_C3W + o * 48;
        #pragma unroll
        for (int i = 0; i < 48; i++) acc = fmaf(w3[i], s[S_P2 + i], acc);
        s[S_FEAT + o] = fmaxf(acc, 0.f);
    }
    __syncwarp();

    // ---- b2 = relu(lfc1_w @ feat + lfc1_b) ----
    {
        float acc = w[OFF_L1B + lane];
        const float* lw = w + OFF_L1W + lane * 64;
        #pragma unroll
        for (int j = 0; j < 64; j++) acc = fmaf(lw[j], s[S_FEAT + j], acc);
        float r = fmaxf(acc, 0.f);
        s[S_B2 + lane] = r;
        out[(long)sample * 96 + 64 + lane] = r;
    }
    __syncwarp();

    // ---- collapsed MHA: v = vw @ b2 + vb;  a = out_w @ v + out_b ----
    {
        float acc = w[OFF_VB + lane];
        const float* vw = w + OFF_VW + lane * 32;
        #pragma unroll
        for (int j = 0; j < 32; j++) acc = fmaf(vw[j], s[S_B2 + j], acc);
        s[S_V + lane] = acc;
    }
    __syncwarp();
    {
        float acc = w[OFF_OB + lane];
        const float* ow = w + OFF_OW + lane * 32;
        #pragma unroll
        for (int j = 0; j < 32; j++) acc = fmaf(ow[j], s[S_V + j], acc);
        out[(long)sample * 96 + 32 + lane] = acc;
    }

    // ---- xf = relu(fc_w @ t[:8] + fc_b) ----
    {
        float acc = w[OFF_FCB + lane];
        const float* fw = w + OFF_FCW + lane * 8;
        #pragma unroll
        for (int j = 0; j < 8; j++) acc = fmaf(fw[j], (float)trow[j], acc);
        out[(long)sample * 96 + lane] = fmaxf(acc, 0.f);
    }
}

extern "C" void kernel_launch(void* const* d_in, const int* in_sizes, int n_in,
                              void* d_out, int out_size)
{
    const int*   t    = (const int*)  d_in[0];
    const int*   pt   = (const int*)  d_in[1];
    const float* c1w  = (const float*)d_in[2];
    const float* c1b  = (const float*)d_in[3];
    const float* c2w  = (const float*)d_in[4];
    const float* c2b  = (const float*)d_in[5];
    const float* c3w  = (const float*)d_in[6];
    const float* c3b  = (const float*)d_in[7];
    const float* l1w  = (const float*)d_in[8];
    const float* l1b  = (const float*)d_in[9];
    const float* fcw  = (const float*)d_in[10];
    const float* fcb  = (const float*)d_in[11];
    // d_in[12] = emb (dead: attention over a single key ignores queries)
    const float* ipw  = (const float*)d_in[13];
    const float* ipb  = (const float*)d_in[14];
    const float* opw  = (const float*)d_in[15];
    const float* opb  = (const float*)d_in[16];

    const int bsz = in_sizes[0] / 232;
    float* out = (float*)d_out;

    // tuple output flattened (out[B,96], board[B,3,22,12]) in order
    const long total_both = (long)bsz * (96 + 792);
    const int write_board = (out_size >= total_both) ? 1 : 0;
    float* board_out = out + (long)bsz * 96;

    const size_t smem = (size_t)(WTOT + WARPS_PER_BLOCK * SCR_STRIDE) * sizeof(float);
    cudaFuncSetAttribute(board_model_kernel,
                         cudaFuncAttributeMaxDynamicSharedMemorySize, (int)smem);

    const int grid = (bsz + WARPS_PER_BLOCK - 1) / WARPS_PER_BLOCK;
    board_model_kernel<<<grid, NTHREADS, smem>>>(
        t, pt, c1w, c1b, c2w, c2b, c3w, c3b, l1w, l1b, fcw, fcb,
        ipw, ipb, opw, opb, out, board_out, bsz, write_board);
}

// round 13
// speedup vs baseline: 1.2779x; 1.2779x over previous
#include <cuda_runtime.h>
#include <cuda_bf16.h>

// ---------------------------------------------------------------------------
// BoardModel: board build + LeNet + (collapsed) MHA + FC head.
//  (1) kv seq-len == 1 -> softmax == 1 -> attention collapses:
//      a_mean = out_w @ (vw @ b2 + vb) + out_b.  emb/pe/q/k are dead code.
//  (2) conv1 ch1/ch2 = constant pad FRAME + 4 piece cells (linear pre-ReLU):
//      frame -> precomputed table F[oc][22][12] (read back as LDS.128);
//      cells -> 5x5 weight stamps; dense conv over ch0 only.
//  (3) Occupancy: SMEM ~55KB/block (ch0-only board, FC weights via
//      __ldg float4) -> 3 blocks/SM (24 warps) vs 2 (16) in the 348us run.
//  (4) conv2 patch rows padded to 8 floats -> LDS.128 loads (-2/3 LDS).
//  (5) board output written per-channel (cheap q/3 indexing).
// One warp per sample; board ch0 at row stride 13 (conflict-free conv1).
// ---------------------------------------------------------------------------

#define WARPS_PER_BLOCK 8
#define NTHREADS (WARPS_PER_BLOCK * 32)

// shared-memory weight offsets (floats)
#define OFF_C1W 0        // 450
#define OFF_C1B 450      // 6
#define OFF_C2W 456      // 2400
#define OFF_C2B 2856     // 16
#define OFF_C3B 2872     // 64
#define OFF_L1B 2936     // 32
#define OFF_VB  2968     // 32
#define OFF_OB  3000     // 32
#define OFF_FRM 3032     // 6*22*12 = 1584 (ch1+ch2 frame conv table)
#define WTOT    4616     // multiple of 4

#define BSTRIDE 13       // board ch0 row stride (bank-conflict-avoiding)
#define P1STRIDE 8       // pooled-conv1 row stride (float4-aligned)

// per-warp scratch offsets (floats)
#define S_BOARD 0                   // 22*13 = 286 (ch0 only)
#define S_P1    288                 // 6*11*8 = 528
#define S_C2    (288+528)           // 16*6*2 = 192
#define S_P2    (S_C2+192)          // 48
#define S_FEAT  (S_P2+48)           // 64
#define S_B2    (S_FEAT+64)         // 32
#define S_V     (S_B2+32)           // 32
#define SCR_STRIDE 1184             // used 1182; multiple of 4

__global__ void __launch_bounds__(NTHREADS, 3)
board_model_kernel(const int* __restrict__ t,
                   const int* __restrict__ piece_table,
                   const float* __restrict__ c1w, const float* __restrict__ c1b,
                   const float* __restrict__ c2w, const float* __restrict__ c2b,
                   const float* __restrict__ c3w, const float* __restrict__ c3b,
                   const float* __restrict__ l1w, const float* __restrict__ l1b,
                   const float* __restrict__ fcw, const float* __restrict__ fcb,
                   const float* __restrict__ ipw, const float* __restrict__ ipb,
                   const float* __restrict__ opw, const float* __restrict__ opb,
                   float* __restrict__ out, float* __restrict__ board_out,
                   int bsz, int write_board)
{
    extern __shared__ float sm[];
    float* w = sm;
    const int tid = threadIdx.x;

    // ---- stage small weights into shared memory ----
    for (int i = tid; i < 450;  i += NTHREADS) w[OFF_C1W + i] = c1w[i];
    for (int i = tid; i < 6;    i += NTHREADS) w[OFF_C1B + i] = c1b[i];
    for (int i = tid; i < 2400; i += NTHREADS) w[OFF_C2W + i] = c2w[i];
    for (int i = tid; i < 16;   i += NTHREADS) w[OFF_C2B + i] = c2b[i];
    for (int i = tid; i < 64;   i += NTHREADS) w[OFF_C3B + i] = c3b[i];
    for (int i = tid; i < 32;   i += NTHREADS) w[OFF_L1B + i] = l1b[i];
    for (int i = tid; i < 32;   i += NTHREADS) w[OFF_VB  + i] = ipb[64 + i];
    for (int i = tid; i < 32;   i += NTHREADS) w[OFF_OB  + i] = opb[i];
    __syncthreads();

    // ---- F[oc][oy][ox]: conv response of (ch1+ch2) pad frame ----
    for (int i = tid; i < 1584; i += NTHREADS) {
        int oc  = i / 264;
        int rem = i % 264;
        int oy  = rem / 12, ox = rem % 12;
        const float* w1k = w + OFF_C1W + (oc * 3 + 1) * 25;
        const float* w2k = w1k + 25;
        float f = 0.f;
        #pragma unroll
        for (int ky = 0; ky < 5; ky++) {
            int iy = oy - 2 + ky;
            if (iy < 0 || iy > 21) continue;
            #pragma unroll
            for (int kx = 0; kx < 5; kx++) {
                int ix = ox - 2 + kx;
                if (ix < 0 || ix > 11) continue;
                if (iy == 21 || ix == 0 || ix == 11)
                    f += w1k[ky * 5 + kx] + w2k[ky * 5 + kx];
            }
        }
        w[OFF_FRM + i] = f;
    }
    __syncthreads();

    const int warp = tid >> 5;
    const int lane = tid & 31;
    const int sample = blockIdx.x * WARPS_PER_BLOCK + warp;
    if (sample >= bsz) return;

    float* s = sm + WTOT + warp * SCR_STRIDE;
    const int* trow = t + sample * 232;

    // ---- build padded board CH0 ONLY [22][13] (col 12 = scratch pad) ----
    for (int p = lane; p < 286; p += 32) {
        int r = p / BSTRIDE;
        int c = p - r * BSTRIDE;
        float v;
        if (c >= 12)                            v = 0.0f;
        else if (r == 21 || c == 0 || c == 11)  v = 1.0f;
        else                                    v = (float)trow[22 + r * 10 + (c - 1)];
        s[S_BOARD + p] = v;
    }

    // ---- piece cells (uniform across lanes; no SMEM scatter needed) ----
    int cX[4], cY1[4], cY2[4], cOK[4];
    {
        const int t1 = trow[1], t2 = trow[2], t3 = trow[3], t4 = trow[4], t8 = trow[8];
        const int* pt = piece_table + ((t8 * 4 + t4) * 16);
        int cells[4];
        int n = 0;
        #pragma unroll
        for (int i = 0; i < 16; i++) { if (n < 4 && pt[i] == 1) cells[n++] = i; }
        #pragma unroll
        for (int i = 0; i < 16; i++) { if (n < 4 && pt[i] != 1) cells[n++] = i; }
        #pragma unroll
        for (int k = 0; k < 4; k++) {
            int cy = cells[k] >> 2, cx = cells[k] & 3;
            int x  = cx + t1 - 2;
            int y  = cy + t2;
            int ny = y + t3;
            cOK[k] = (y >= 0 && ny >= 0 && x >= 0 && x < 10);
            cX[k]  = x + 1;
            cY1[k] = y;
            cY2[k] = ny;
        }
    }
    __syncwarp();

    // ---- board output [3][22][12]: ch0 from SMEM, ch1/ch2 reconstructed.
    // Per-channel loops: q in [0,66) float4s; r = q/3, c0 = 4*(q%3). ----
    if (write_board) {
        int key1[4], key2[4];   // packed r*16+col; -1 if dropped
        #pragma unroll
        for (int k = 0; k < 4; k++) {
            key1[k] = (cOK[k] && cY1[k] < 21) ? (cY1[k] * 16 + cX[k]) : -1;
            key2[k] = (cOK[k] && cY2[k] < 21) ? (cY2[k] * 16 + cX[k]) : -1;
        }
        float4* bo4 = (float4*)(board_out + (long)sample * 792);
        // ch0: copy from SMEM
        for (int q = lane; q < 66; q += 32) {
            int r  = q / 3;
            int c0 = (q - r * 3) * 4;
            const float* src = &s[S_BOARD + r * BSTRIDE + c0];
            bo4[q] = make_float4(src[0], src[1], src[2], src[3]);
        }
        // ch1, ch2: frame + piece cells, register-reconstructed
        #pragma unroll
        for (int ch = 1; ch <= 2; ch++) {
            const int* key = (ch == 1) ? key1 : key2;
            for (int q = lane; q < 66; q += 32) {
                int r  = q / 3;
                int c0 = (q - r * 3) * 4;
                float vv[4];
                #pragma unroll
                for (int c = 0; c < 4; c++) {
                    int col = c0 + c;
                    bool e = (r == 21) || (col == 0) || (col == 11);
                    int kk = r * 16 + col;
                    #pragma unroll
                    for (int k = 0; k < 4; k++) e = e || (kk == key[k]);
                    vv[c] = e ? 1.0f : 0.0f;
                }
                bo4[ch * 66 + q] = make_float4(vv[0], vv[1], vv[2], vv[3]);
            }
        }
    }

    // ---- conv1 (ch0 dense + frame table + piece stamps) + ReLU + pool ----
    // Task = (oc, py, px-pair): 198 tasks; 8 conv outputs per task.
    for (int tp = lane; tp < 198; tp += 32) {
        int oc  = tp / 33;
        int rem = tp % 33;
        int py  = rem / 3, pxp = rem % 3;
        int y0 = 2 * py;
        int x0 = 4 * pxp;

        // frame contribution: two aligned LDS.128 (rows y0, y0+1; 4 cols)
        const float* Foc = w + OFF_FRM + oc * 264;
        float4 f0 = *(const float4*)(Foc + y0 * 12 + x0);
        float4 f1 = *(const float4*)(Foc + (y0 + 1) * 12 + x0);
        float acc[2][4];
        acc[0][0] = f0.x; acc[0][1] = f0.y; acc[0][2] = f0.z; acc[0][3] = f0.w;
        acc[1][0] = f1.x; acc[1][1] = f1.y; acc[1][2] = f1.z; acc[1][3] = f1.w;

        // dense channel 0
        {
            float patch[6][8];
            #pragma unroll
            for (int dy = 0; dy < 6; dy++) {
                int iy = y0 - 2 + dy;
                #pragma unroll
                for (int dx = 0; dx < 8; dx++) {
                    int ix = x0 - 2 + dx;
                    patch[dy][dx] = (iy >= 0 && iy < 22 && ix >= 0 && ix < 12)
                                  ? s[S_BOARD + iy * BSTRIDE + ix] : 0.f;
                }
            }
            const float* wk = w + OFF_C1W + (oc * 3) * 25;
            #pragma unroll
            for (int ky = 0; ky < 5; ky++) {
                #pragma unroll
                for (int kx = 0; kx < 5; kx++) {
                    float wv = wk[ky * 5 + kx];
                    #pragma unroll
                    for (int r = 0; r < 2; r++) {
                        acc[r][0] = fmaf(wv, patch[ky + r][kx    ], acc[r][0]);
                        acc[r][1] = fmaf(wv, patch[ky + r][kx + 1], acc[r][1]);
                        acc[r][2] = fmaf(wv, patch[ky + r][kx + 2], acc[r][2]);
                        acc[r][3] = fmaf(wv, patch[ky + r][kx + 3], acc[r][3]);
                    }
                }
            }
        }

        // piece-cell stamps for ch1, ch2 (cells interior: rows<21, cols 1..10)
        const float* w1k = w + OFF_C1W + (oc * 3 + 1) * 25;
        const float* w2k = w1k + 25;
        #pragma unroll
        for (int k = 0; k < 4; k++) {
            if (!cOK[k]) continue;
            int dxx = cX[k] - x0 + 2;
            if ((unsigned)dxx > 7u) continue;
            int dy1 = cY1[k] - y0 + 2;
            if (cY1[k] < 21 && (unsigned)dy1 <= 5u) {
                #pragma unroll
                for (int r = 0; r < 2; r++) {
                    int oy = dy1 - r;
                    if ((unsigned)oy < 5u) {
                        #pragma unroll
                        for (int c = 0; c < 4; c++) {
                            int ox = dxx - c;
                            if ((unsigned)ox < 5u) acc[r][c] += w1k[oy * 5 + ox];
                        }
                    }
                }
            }
            int dy2 = cY2[k] - y0 + 2;
            if (cY2[k] < 21 && (unsigned)dy2 <= 5u) {
                #pragma unroll
                for (int r = 0; r < 2; r++) {
                    int oy = dy2 - r;
                    if ((unsigned)oy < 5u) {
                        #pragma unroll
                        for (int c = 0; c < 4; c++) {
                            int ox = dxx - c;
                            if ((unsigned)ox < 5u) acc[r][c] += w2k[oy * 5 + ox];
                        }
                    }
                }
            }
        }

        float bb = w[OFF_C1B + oc];
        float p0 = 0.25f * (fmaxf(acc[0][0] + bb, 0.f) + fmaxf(acc[0][1] + bb, 0.f) +
                            fmaxf(acc[1][0] + bb, 0.f) + fmaxf(acc[1][1] + bb, 0.f));
        float p1 = 0.25f * (fmaxf(acc[0][2] + bb, 0.f) + fmaxf(acc[0][3] + bb, 0.f) +
                            fmaxf(acc[1][2] + bb, 0.f) + fmaxf(acc[1][3] + bb, 0.f));
        s[S_P1 + (oc * 11 + py) * P1STRIDE + 2 * pxp    ] = p0;
        s[S_P1 + (oc * 11 + py) * P1STRIDE + 2 * pxp + 1] = p1;
    }
    __syncwarp();

    // ---- conv2 (6->16, 5x5, valid) + ReLU, rows 0..5 (row 6 pooled away).
    // Task = (oc, half), one per lane. P1 rows float4-loaded (LDS.128). ----
    {
        int oc   = lane >> 1;
        int half = lane & 1;
        int oy0  = 3 * half;
        float bb = w[OFF_C2B + oc];
        float acc[3][2];
        #pragma unroll
        for (int r = 0; r < 3; r++) { acc[r][0] = bb; acc[r][1] = bb; }
        const float* w2 = w + OFF_C2W + oc * 150;
        #pragma unroll
        for (int ci = 0; ci < 6; ci++) {
            float patch[7][6];
            #pragma unroll
            for (int dy = 0; dy < 7; dy++) {
                const float* row = &s[S_P1 + (ci * 11 + oy0 + dy) * P1STRIDE];
                float4 a0 = *(const float4*)(row);
                float4 a1 = *(const float4*)(row + 4);
                patch[dy][0] = a0.x; patch[dy][1] = a0.y; patch[dy][2] = a0.z;
                patch[dy][3] = a0.w; patch[dy][4] = a1.x; patch[dy][5] = a1.y;
            }
            const float* wc = &w2[ci * 25];
            #pragma unroll
            for (int ky = 0; ky < 5; ky++) {
                #pragma unroll
                for (int kx = 0; kx < 5; kx++) {
                    float wv = wc[ky * 5 + kx];
                    #pragma unroll
                    for (int r = 0; r < 3; r++) {
                        acc[r][0] = fmaf(wv, patch[r + ky][kx    ], acc[r][0]);
                        acc[r][1] = fmaf(wv, patch[r + ky][kx + 1], acc[r][1]);
                    }
                }
            }
        }
        #pragma unroll
        for (int r = 0; r < 3; r++) {
            s[S_C2 + (oc * 6 + oy0 + r) * 2 + 0] = fmaxf(acc[r][0], 0.f);
            s[S_C2 + (oc * 6 + oy0 + r) * 2 + 1] = fmaxf(acc[r][1], 0.f);
        }
    }
    __syncwarp();

    // ---- avgpool2 on conv2 -> [16][3] ----
    for (int p = lane; p < 48; p += 32) {
        int oc = p / 3, py = p - oc * 3;
        const float* c2 = &s[S_C2 + (oc * 6 + 2 * py) * 2];
        s[S_P2 + p] = 0.25f * (c2[0] + c2[1] + c2[2] + c2[3]);
    }
    __syncwarp();

    // ---- conv3 (16->64, 3x1) + ReLU -> feat[64]; weights via LDG.128 ----
    #pragma unroll
    for (int k = 0; k < 2; k++) {
        int o = lane + k * 32;
        float acc = w[OFF_C3B + o];
        const float4* w3 = (const float4*)(c3w + o * 48);
        #pragma unroll
        for (int i = 0; i < 12; i++) {
            float4 wv = __ldg(w3 + i);
            const float* p2 = &s[S_P2 + i * 4];
            acc = fmaf(wv.x, p2[0], acc);
            acc = fmaf(wv.y, p2[1], acc);
            acc = fmaf(wv.z, p2[2], acc);
            acc = fmaf(wv.w, p2[3], acc);
        }
        s[S_FEAT + o] = fmaxf(acc, 0.f);
    }
    __syncwarp();

    // ---- b2 = relu(lfc1_w @ feat + b); weights via LDG.128 ----
    {
        float acc = w[OFF_L1B + lane];
        const float4* lw = (const float4*)(l1w + lane * 64);
        #pragma unroll
        for (int i = 0; i < 16; i++) {
            float4 wv = __ldg(lw + i);
            const float* f = &s[S_FEAT + i * 4];
            acc = fmaf(wv.x, f[0], acc);
            acc = fmaf(wv.y, f[1], acc);
            acc = fmaf(wv.z, f[2], acc);
            acc = fmaf(wv.w, f[3], acc);
        }
        float r = fmaxf(acc, 0.f);
        s[S_B2 + lane] = r;
        out[sample * 96 + 64 + lane] = r;
    }
    __syncwarp();

    // ---- collapsed MHA: v = vw@b2+vb; a = out_w@v+out_b (LDG.128) ----
    {
        float acc = w[OFF_VB + lane];
        const float4* vw = (const float4*)(ipw + (64 + lane) * 32);
        #pragma unroll
        for (int i = 0; i < 8; i++) {
            float4 wv = __ldg(vw + i);
            const float* b2 = &s[S_B2 + i * 4];
            acc = fmaf(wv.x, b2[0], acc);
            acc = fmaf(wv.y, b2[1], acc);
            acc = fmaf(wv.z, b2[2], acc);
            acc = fmaf(wv.w, b2[3], acc);
        }
        s[S_V + lane] = acc;
    }
    __syncwarp();
    {
        float acc = w[OFF_OB + lane];
        const float4* ow = (const float4*)(opw + lane * 32);
        #pragma unroll
        for (int i = 0; i < 8; i++) {
            float4 wv = __ldg(ow + i);
            const float* v = &s[S_V + i * 4];
            acc = fmaf(wv.x, v[0], acc);
            acc = fmaf(wv.y, v[1], acc);
            acc = fmaf(wv.z, v[2], acc);
            acc = fmaf(wv.w, v[3], acc);
        }
        out[sample * 96 + 32 + lane] = acc;
    }

    // ---- xf = relu(fc_w @ t[:8] + fc_b); weights via LDG.128 ----
    {
        float acc = __ldg(fcb + lane);
        const float4* fw = (const float4*)(fcw + lane * 8);
        float4 w0 = __ldg(fw), w1 = __ldg(fw + 1);
        acc = fmaf(w0.x, (float)trow[0], acc);
        acc = fmaf(w0.y, (float)trow[1], acc);
        acc = fmaf(w0.z, (float)trow[2], acc);
        acc = fmaf(w0.w, (float)trow[3], acc);
        acc = fmaf(w1.x, (float)trow[4], acc);
        acc = fmaf(w1.y, (float)trow[5], acc);
        acc = fmaf(w1.z, (float)trow[6], acc);
        acc = fmaf(w1.w, (float)trow[7], acc);
        out[sample * 96 + lane] = fmaxf(acc, 0.f);
    }
}

extern "C" void kernel_launch(void* const* d_in, const int* in_sizes, int n_in,
                              void* d_out, int out_size)
{
    const int*   t    = (const int*)  d_in[0];
    const int*   pt   = (const int*)  d_in[1];
    const float* c1w  = (const float*)d_in[2];
    const float* c1b  = (const float*)d_in[3];
    const float* c2w  = (const float*)d_in[4];
    const float* c2b  = (const float*)d_in[5];
    const float* c3w  = (const float*)d_in[6];
    const float* c3b  = (const float*)d_in[7];
    const float* l1w  = (const float*)d_in[8];
    const float* l1b  = (const float*)d_in[9];
    const float* fcw  = (const float*)d_in[10];
    const float* fcb  = (const float*)d_in[11];
    // d_in[12] = emb (dead)
    const float* ipw  = (const float*)d_in[13];
    const float* ipb  = (const float*)d_in[14];
    const float* opw  = (const float*)d_in[15];
    const float* opb  = (const float*)d_in[16];

    const int bsz = in_sizes[0] / 232;
    float* out = (float*)d_out;

    const long total_both = (long)bsz * (96 + 792);
    const int write_board = (out_size >= total_both) ? 1 : 0;
    float* board_out = out + (long)bsz * 96;

    const size_t smem = (size_t)(WTOT + WARPS_PER_BLOCK * SCR_STRIDE) * sizeof(float);
    cudaFuncSetAttribute(board_model_kernel,
                         cudaFuncAttributeMaxDynamicSharedMemorySize, (int)smem);

    const int grid = (bsz + WARPS_PER_BLOCK - 1) / WARPS_PER_BLOCK;
    board_model_kernel<<<grid, NTHREADS, smem>>>(
        t, pt, c1w, c1b, c2w, c2b, c3w, c3b, l1w, l1b, fcw, fcb,
        ipw, ipb, opw, opb, out, board_out, bsz, write_board);
}